// round 6
// baseline (speedup 1.0000x reference)
#include <cuda_runtime.h>
#include <cuda_fp16.h>
#include <cstdint>
#include <cstddef>

#define B_   32
#define DIN  64
#define DS   1024
#define L_   2048
#define PP   128
#define TC   32
#define NC   (L_ / TC)
#define AS   70      // wsA/wsB row stride in halves (35 words, odd -> CF)

// stage: [2 par][2 bb][PP p][TC t] fp16, rows 64B, 16B blocks XOR-swizzled:
//   physical block pb = (b + (p>>1)) & 3,  b = t>>3
#define STAGE_BYTES (2 * 2 * PP * TC * 2)    // 32768
#define WSA_BYTES   (2 * 2 * TC * AS * 2)    // 17920
#define WSB_BYTES   (PP * AS * 2)            // 17920
#define SMEM_TOTAL  (STAGE_BYTES + WSA_BYTES + WSB_BYTES)   // 68608

#define BAR_SYNC(id, cnt) asm volatile("bar.sync %0, %1;" :: "r"(id), "r"(cnt) : "memory")

__global__ __launch_bounds__(512, 1)
void esn_fused(const float* __restrict__ u,
               const float* __restrict__ w_in,
               const float* __restrict__ w_hh,
               const float* __restrict__ bias,
               float* __restrict__ out) {
    extern __shared__ unsigned char smem_raw[];
    __half* stage = (__half*)smem_raw;                               // [2][2][PP][TC]
    __half* wsA   = (__half*)(smem_raw + STAGE_BYTES);               // [2][2][TC][AS]
    __half* wsB   = (__half*)(smem_raw + STAGE_BYTES + WSA_BYTES);   // [PP][AS]

    const int tid   = threadIdx.x;
    const int p0    = blockIdx.x * PP;
    const int bpair = blockIdx.y;            // b = 2*bpair, 2*bpair+1

    // cooperative wsB fill: wsB[p][k] = fp16(w_in[p0+p][k])
    for (int i = tid; i < PP * DIN; i += 512) {
        int p = i >> 6, k = i & 63;
        wsB[p * AS + k] = __float2half_rn(w_in[(size_t)(p0 + p) * DIN + k]);
    }
    __syncthreads();

    if (tid < 256) {
        // ===================== PRODUCERS (8 warps) =========================
        // warp -> (bbc, mh, nh): m16 x n64 tile; A shared by 2 warps only
        const int w    = tid >> 5;
        const int bbc  = w >> 2;
        const int mh   = (w >> 1) & 1;
        const int nh   = w & 1;
        const int lane = tid & 31;
        const int g = lane >> 2, t = lane & 3;
        const float* ub0 = u + (size_t)(bpair * 2) * DIN * L_;

        // chunk-invariant B fragments: 4 kt x 8 n-tiles x 2 regs
        uint32_t bfr[4][8][2];
        #pragma unroll
        for (int kt = 0; kt < 4; kt++)
            #pragma unroll
            for (int in = 0; in < 8; in++) {
                const __half* wp = wsB + (size_t)(nh * 64 + in * 8 + g) * AS + kt * 16 + 2 * t;
                bfr[kt][in][0] = *(const uint32_t*)(wp);
                bfr[kt][in][1] = *(const uint32_t*)(wp + 8);
            }

        // prefetch chunk 0 (lane varies l -> coalesced)
        float uv[16];
        #pragma unroll
        for (int j = 0; j < 16; j++) {
            int i = tid + j * 256;
            int bb = i >> 11, h = (i >> 5) & 63, l = i & 31;
            uv[j] = ub0[(size_t)(bb * DIN + h) * L_ + l];
        }

        for (int it = 0; it <= NC; ++it) {
            if (it < NC) {
                const int par = it & 1;

                // store prefetched chunk to wsA[par][bb][l][h]
                #pragma unroll
                for (int j = 0; j < 16; j++) {
                    int i = tid + j * 256;
                    int bb = i >> 11, h = (i >> 5) & 63, l = i & 31;
                    wsA[((size_t)(par * 2 + bb) * TC + l) * AS + h] = __float2half_rn(uv[j]);
                }
                BAR_SYNC(7, 256);

                // prefetch next chunk (hidden under MMA + epilogue)
                if (it + 1 < NC) {
                    const int lc = (it + 1) * TC;
                    #pragma unroll
                    for (int j = 0; j < 16; j++) {
                        int i = tid + j * 256;
                        int bb = i >> 11, h = (i >> 5) & 63, l = i & 31;
                        uv[j] = ub0[(size_t)(bb * DIN + h) * L_ + lc + l];
                    }
                }

                float acc[8][4];
                #pragma unroll
                for (int in = 0; in < 8; in++)
                    #pragma unroll
                    for (int q = 0; q < 4; q++) acc[in][q] = 0.f;

                const __half* wa = wsA + ((size_t)(par * 2 + bbc) * TC + mh * 16) * AS;
                #pragma unroll
                for (int kt = 0; kt < 4; kt++) {
                    const __half* rp = wa + (size_t)g * AS + kt * 16 + 2 * t;
                    uint32_t a0 = *(const uint32_t*)(rp);
                    uint32_t a1 = *(const uint32_t*)(rp + 8 * AS);
                    uint32_t a2 = *(const uint32_t*)(rp + 8);
                    uint32_t a3 = *(const uint32_t*)(rp + 8 * AS + 8);
                    #pragma unroll
                    for (int in = 0; in < 8; in++)
                        asm volatile(
                            "mma.sync.aligned.m16n8k16.row.col.f32.f16.f16.f32 "
                            "{%0,%1,%2,%3}, {%4,%5,%6,%7}, {%8,%9}, {%0,%1,%2,%3};"
                            : "+f"(acc[in][0]), "+f"(acc[in][1]),
                              "+f"(acc[in][2]), "+f"(acc[in][3])
                            : "r"(a0), "r"(a1), "r"(a2), "r"(a3),
                              "r"(bfr[kt][in][0]), "r"(bfr[kt][in][1]));
                }

                // epilogue: movmatrix fragment transpose -> fp16 stage [p][t]
                __half* stg = stage + (size_t)(par * 2 + bbc) * PP * TC;
                #pragma unroll
                for (int in = 0; in < 8; in++) {
                    const int pl = nh * 64 + in * 8 + g;   // p row after trans
                    __half2 h0 = __floats2half2_rn(acc[in][0], acc[in][1]); // rows g   (l blk mh*2)
                    __half2 h1 = __floats2half2_rn(acc[in][2], acc[in][3]); // rows g+8 (l blk mh*2+1)
                    uint32_t m0, m1;
                    asm("movmatrix.sync.aligned.m8n8.trans.b16 %0, %1;"
                        : "=r"(m0) : "r"(*(uint32_t*)&h0));
                    asm("movmatrix.sync.aligned.m8n8.trans.b16 %0, %1;"
                        : "=r"(m1) : "r"(*(uint32_t*)&h1));
                    const int sw  = (pl >> 1) & 3;
                    const int pb0 = (mh * 2 + sw) & 3;
                    const int pb1 = (mh * 2 + 1 + sw) & 3;
                    *(uint32_t*)(stg + (size_t)pl * TC + pb0 * 8 + 2 * t) = m0;
                    *(uint32_t*)(stg + (size_t)pl * TC + pb1 * 8 + 2 * t) = m1;
                }
            }
            BAR_SYNC(0, 512);   // lockstep handoff (carries memory fence)
        }
    } else {
        // ===================== CONSUMERS (8 warps) =========================
        const int ct = tid - 256;
        const int cb = ct >> 7;              // batch half
        const int cp = ct & 127;             // p local
        const int b  = bpair * 2 + cb;
        const int p  = p0 + cp;
        const float d  = w_hh[(size_t)p * DS + p];
        const float bi = bias[p];
        float* ob = out + (size_t)b * DS * L_;
        const int sw = (cp >> 1) & 3;
        const int wc = (ct >> 5) & 3;        // consumer warp within half
        const int lane = ct & 31;
        const int hi = lane >> 4, lt = lane & 15;

        float x = 0.f;
        for (int it = 0; it <= NC; ++it) {
            if (it >= 1) {
                const int c   = it - 1;
                const int par = c & 1;
                __half* row = stage + ((size_t)(par * 2 + cb) * PP + cp) * TC;

                // vector load uproj row (swizzled blocks), unpack + bias
                float upb[TC];
                #pragma unroll
                for (int pb = 0; pb < 4; pb++) {
                    uint4 v = *(const uint4*)(row + pb * 8);
                    const int bl = (pb - sw) & 3;
                    const __half2* hp = (const __half2*)&v;
                    #pragma unroll
                    for (int k = 0; k < 4; k++) {
                        float2 f = __half22float2(hp[k]);
                        upb[bl * 8 + 2 * k]     = f.x + bi;
                        upb[bl * 8 + 2 * k + 1] = f.y + bi;
                    }
                }

                // serial chain, pack x to fp16, STS.128 every 8 steps
                #pragma unroll
                for (int tb = 0; tb < 4; tb++) {
                    uint32_t pk[4];
                    #pragma unroll
                    for (int k = 0; k < 4; k++) {
                        float z = fmaf(x, d, upb[tb * 8 + 2 * k]);
                        float th;
                        asm("tanh.approx.f32 %0, %1;" : "=f"(th) : "f"(z));
                        float xe = fmaf(0.5f, th, 0.5f * x);
                        z = fmaf(xe, d, upb[tb * 8 + 2 * k + 1]);
                        asm("tanh.approx.f32 %0, %1;" : "=f"(th) : "f"(z));
                        x = fmaf(0.5f, th, 0.5f * xe);
                        __half2 h2 = __floats2half2_rn(xe, x);
                        pk[k] = *(uint32_t*)&h2;
                    }
                    const int pb = (tb + sw) & 3;
                    *(uint4*)(row + pb * 8) = make_uint4(pk[0], pk[1], pk[2], pk[3]);
                }
                BAR_SYNC(5 + cb, 128);           // x visible within b-half

                // transpose: 2 p-rows per instr, half2 -> float2 -> STG.64
                const int lc = c * TC;
                const __half* stg = stage + (size_t)(par * 2 + cb) * PP * TC;
                #pragma unroll
                for (int j = 0; j < 16; j++) {
                    const int pr = wc * 32 + 2 * j + hi;
                    const int bl = lt >> 2;
                    const int pbr = (bl + ((pr >> 1) & 3)) & 3;
                    __half2 hv = *(const __half2*)(stg + (size_t)pr * TC + pbr * 8 + 2 * (lt & 3));
                    float2 f = __half22float2(hv);
                    *(float2*)(ob + (size_t)(p0 + pr) * L_ + lc + 2 * lt) = f;
                }
            }
            BAR_SYNC(0, 512);
        }
    }
}

extern "C" void kernel_launch(void* const* d_in, const int* in_sizes, int n_in,
                              void* d_out, int out_size) {
    const float* u    = (const float*)d_in[0];  // [32, 64, 2048]
    const float* w_in = (const float*)d_in[1];  // [1024, 64]
    const float* w_hh = (const float*)d_in[2];  // [1024, 1024]
    const float* bias = (const float*)d_in[3];  // [1024]
    float* out = (float*)d_out;                 // [32, 1024, 2048]

    cudaFuncSetAttribute(esn_fused, cudaFuncAttributeMaxDynamicSharedMemorySize,
                         SMEM_TOTAL);
    dim3 g(DS / PP, B_ / 2);                    // 8 x 16 = 128 blocks, 1 wave
    esn_fused<<<g, 512, SMEM_TOTAL>>>(u, w_in, w_hh, bias, out);
}